// round 1
// baseline (speedup 1.0000x reference)
#include <cuda_runtime.h>

#define B_      4
#define AT      1024
#define NBR     32
#define FN      128
#define FE      128
#define ZIN     384
#define NATOMS  (B_*AT)        // 4096
#define NEDGE   (NATOMS*NBR)   // 131072

// -------- device scratch (no allocation allowed) --------
__device__ float g_h[2][NATOMS*FN];             // ping-pong node features
__device__ float g_e[(size_t)NEDGE*FE];          // edge features (64 MB)
__device__ float g_A[NATOMS*256];                // per-atom hi@W[0:128] + bias (F|C fused)

__device__ __forceinline__ float sigm_(float x){ return 1.0f/(1.0f+expf(-x)); }
// matches jnp.logaddexp(x, 0)
__device__ __forceinline__ float sp_(float x){ return fmaxf(x,0.f)+log1pf(expf(-fabsf(x))); }

// -------------------- init kernels --------------------
__global__ void k_init_h(const int* __restrict__ Z, const float* __restrict__ emb){
  int a = blockIdx.x; int t = threadIdx.x;
  g_h[0][a*FN + t] = emb[Z[a]*FN + t];
}

__global__ void k_init_e(const float* __restrict__ dist){
  int eix = blockIdx.x; int c = threadIdx.x;
  float d = dist[eix];
  const float step = 5.5f/127.0f;
  float mu = c*step;
  float coeff = -0.5f/(step*step);
  float dd = d - mu;
  g_e[(size_t)eix*FE + c] = expf(coeff*dd*dd);
}

// ---------- per-atom hi-part GEMM: g_A = h_i @ W[0:128,:] + bias ----------
__global__ __launch_bounds__(256) void k_pre(int hsel,
    const float* __restrict__ Wf, const float* __restrict__ Wc,
    const float* __restrict__ bf, const float* __restrict__ bc){
  int a = blockIdx.x; int t = threadIdx.x;
  __shared__ float hs[FN];
  if (t < FN) hs[t] = g_h[hsel][a*FN + t];
  __syncthreads();
  int c = t & 127;
  const float* W = (t < 128) ? Wf : Wc;
  float acc0=0.f, acc1=0.f, acc2=0.f, acc3=0.f;
  #pragma unroll 8
  for (int k = 0; k < 128; k += 4){
    acc0 = fmaf(hs[k+0], W[(k+0)*128 + c], acc0);
    acc1 = fmaf(hs[k+1], W[(k+1)*128 + c], acc1);
    acc2 = fmaf(hs[k+2], W[(k+2)*128 + c], acc2);
    acc3 = fmaf(hs[k+3], W[(k+3)*128 + c], acc3);
  }
  float bias = (t < 128) ? bf[c] : bc[c];
  g_A[a*256 + t] = acc0+acc1+acc2+acc3 + bias;
}

// ---------- main edge GEMM + activation (+ neighbor reduce) ----------
// Block = one atom. C[32 neighbors x 256 cols (F|C)], K = 256 ([hj | e]).
// MODE 0: node update -> g_h[1-hsel] = g_h[hsel] + sum_n sig(F)*sp(C)
// MODE 1: edge update -> g_e += sig(F)*sp(C)
#define SMEM_MSG ((256*33 + 64*256)*4)
template<int MODE>
__global__ __launch_bounds__(256,2) void k_msg(int hsel,
    const float* __restrict__ Wf, const float* __restrict__ Wc,
    const int* __restrict__ nbr_idx){
  extern __shared__ float smem[];
  float* zT = smem;              // [256 k][33] (pad -> conflict-free), reused as S later
  float* Wt = smem + 256*33;     // [64 k][256 c]

  int a    = blockIdx.x;
  int b    = a >> 10;
  int tid  = threadIdx.x;
  int w    = tid >> 5, lane = tid & 31;
  const float* h_in = g_h[hsel];

  // ---- load z^T: k<128 = h[neighbor], k>=128 = e[edge] ----
  #pragma unroll
  for (int q = 0; q < 4; q++){
    int n = w + q*8;
    int j = nbr_idx[a*NBR + n];
    const float* hj = h_in + ((size_t)(b*AT + j))*FN;
    const float* er = g_e  + ((size_t)(a*NBR + n))*FE;
    #pragma unroll
    for (int kk = 0; kk < 4; kk++){
      int k = lane + kk*32;
      zT[k*33 + n]        = hj[k];
      zT[(128+k)*33 + n]  = er[k];
    }
  }
  __syncthreads();

  int tr4 = (tid >> 5) * 4;   // row base (neighbor)
  int tc8 = (tid & 31) * 8;   // col base
  float acc[4][8];
  #pragma unroll
  for (int r = 0; r < 4; r++)
    #pragma unroll
    for (int c = 0; c < 8; c++) acc[r][c] = 0.f;

  const float* Wf_s = Wf + 128*128;   // skip the hi rows
  const float* Wc_s = Wc + 128*128;

  for (int kt = 0; kt < 4; kt++){
    // stage W tile [64 x 256] (cols: 0..127 from Wf, 128..255 from Wc)
    #pragma unroll
    for (int i = 0; i < 16; i++){
      int lin = i*256 + tid;          // float4 index
      int kk  = lin >> 6;
      int c4  = (lin & 63) << 2;
      int k   = kt*64 + kk;
      const float* src = (c4 < 128) ? (Wf_s + k*128 + c4)
                                    : (Wc_s + k*128 + (c4-128));
      *(float4*)&Wt[kk*256 + c4] = *(const float4*)src;
    }
    __syncthreads();
    #pragma unroll 8
    for (int kk = 0; kk < 64; kk++){
      int k = kt*64 + kk;
      float av[4];
      av[0] = zT[k*33 + tr4 + 0];
      av[1] = zT[k*33 + tr4 + 1];
      av[2] = zT[k*33 + tr4 + 2];
      av[3] = zT[k*33 + tr4 + 3];
      float4 b0 = *(float4*)&Wt[kk*256 + tc8];
      float4 b1 = *(float4*)&Wt[kk*256 + tc8 + 4];
      #pragma unroll
      for (int r = 0; r < 4; r++){
        acc[r][0] = fmaf(av[r], b0.x, acc[r][0]);
        acc[r][1] = fmaf(av[r], b0.y, acc[r][1]);
        acc[r][2] = fmaf(av[r], b0.z, acc[r][2]);
        acc[r][3] = fmaf(av[r], b0.w, acc[r][3]);
        acc[r][4] = fmaf(av[r], b1.x, acc[r][4]);
        acc[r][5] = fmaf(av[r], b1.y, acc[r][5]);
        acc[r][6] = fmaf(av[r], b1.z, acc[r][6]);
        acc[r][7] = fmaf(av[r], b1.w, acc[r][7]);
      }
    }
    __syncthreads();
  }

  // ---- spill C to smem (reuse zT region) for the epilogue ----
  float* S = zT;   // [32][256], 8192 floats <= 8448 available
  #pragma unroll
  for (int r = 0; r < 4; r++){
    *(float4*)&S[(tr4+r)*256 + tc8]     = make_float4(acc[r][0],acc[r][1],acc[r][2],acc[r][3]);
    *(float4*)&S[(tr4+r)*256 + tc8 + 4] = make_float4(acc[r][4],acc[r][5],acc[r][6],acc[r][7]);
  }
  __syncthreads();

  if (MODE == 0){
    if (tid < 128){
      int c = tid;
      float aF = g_A[a*256 + c];
      float aC = g_A[a*256 + 128 + c];
      float s = 0.f;
      #pragma unroll 8
      for (int n = 0; n < NBR; n++){
        float F = S[n*256 + c]       + aF;
        float C = S[n*256 + 128 + c] + aC;
        s += sigm_(F) * sp_(C);
      }
      g_h[1-hsel][a*FN + c] = h_in[a*FN + c] + s;
    }
  } else {
    int c    = tid & 127;
    int half = tid >> 7;
    float aF = g_A[a*256 + c];
    float aC = g_A[a*256 + 128 + c];
    #pragma unroll
    for (int q = 0; q < 16; q++){
      int n = half*16 + q;
      float F = S[n*256 + c]       + aF;
      float C = S[n*256 + 128 + c] + aC;
      size_t ei = (size_t)(a*NBR + n)*FE + c;
      g_e[ei] += sigm_(F) * sp_(C);
    }
  }
}

// ---------- force-magnitude mapping + force reduction ----------
#define SMEM_FIN ((32*128 + 128*64 + 32)*4)
__global__ __launch_bounds__(256) void k_final(
    const float* __restrict__ Wo1, const float* __restrict__ bo1,
    const float* __restrict__ Wo2, const float* __restrict__ bo2,
    const float* __restrict__ unit, float* __restrict__ out){
  extern __shared__ float smem[];
  float* es = smem;              // [32][128]
  float* w1 = smem + 32*128;     // [128][64]
  float* fm = w1 + 128*64;       // [32]
  int a = blockIdx.x; int tid = threadIdx.x;
  #pragma unroll
  for (int i = 0; i < 16; i++) es[i*256 + tid] = g_e[(size_t)a*NBR*FE + i*256 + tid];
  #pragma unroll
  for (int i = 0; i < 32; i++) w1[i*256 + tid] = Wo1[i*256 + tid];
  __syncthreads();

  int n  = tid >> 3;
  int m0 = (tid & 7) * 8;
  float acc[8];
  #pragma unroll
  for (int m = 0; m < 8; m++) acc[m] = bo1[m0+m];
  for (int k = 0; k < 128; k++){
    float ek = es[n*128 + k];
    float4 wa = *(float4*)&w1[k*64 + m0];
    float4 wb = *(float4*)&w1[k*64 + m0 + 4];
    acc[0] = fmaf(ek, wa.x, acc[0]);
    acc[1] = fmaf(ek, wa.y, acc[1]);
    acc[2] = fmaf(ek, wa.z, acc[2]);
    acc[3] = fmaf(ek, wa.w, acc[3]);
    acc[4] = fmaf(ek, wb.x, acc[4]);
    acc[5] = fmaf(ek, wb.y, acc[5]);
    acc[6] = fmaf(ek, wb.z, acc[6]);
    acc[7] = fmaf(ek, wb.w, acc[7]);
  }
  float part = 0.f;
  #pragma unroll
  for (int m = 0; m < 8; m++) part += sp_(acc[m]) * Wo2[m0+m];
  part += __shfl_xor_sync(0xffffffffu, part, 4);
  part += __shfl_xor_sync(0xffffffffu, part, 2);
  part += __shfl_xor_sync(0xffffffffu, part, 1);
  if ((tid & 7) == 0) fm[n] = part + bo2[0];
  __syncthreads();
  if (tid < 3){
    float s = 0.f;
    #pragma unroll 8
    for (int n2 = 0; n2 < NBR; n2++)
      s += fm[n2] * unit[((size_t)a*NBR + n2)*3 + tid];
    out[a*3 + tid] = s;
  }
}

extern "C" void kernel_launch(void* const* d_in, const int* in_sizes, int n_in,
                              void* d_out, int out_size){
  const int*   Z    = (const int*)  d_in[0];
  const int*   nbr  = (const int*)  d_in[1];
  const float* dist = (const float*)d_in[2];
  const float* unit = (const float*)d_in[3];
  const float* emb  = (const float*)d_in[4];
  const float* Wnf  = (const float*)d_in[5];
  const float* bnf  = (const float*)d_in[6];
  const float* Wnc  = (const float*)d_in[7];
  const float* bnc  = (const float*)d_in[8];
  const float* Wef  = (const float*)d_in[9];
  const float* bef  = (const float*)d_in[10];
  const float* Wec  = (const float*)d_in[11];
  const float* bec  = (const float*)d_in[12];
  const float* Wo1  = (const float*)d_in[13];
  const float* bo1  = (const float*)d_in[14];
  const float* Wo2  = (const float*)d_in[15];
  const float* bo2  = (const float*)d_in[16];
  float* out = (float*)d_out;

  cudaFuncSetAttribute(k_msg<0>, cudaFuncAttributeMaxDynamicSharedMemorySize, SMEM_MSG);
  cudaFuncSetAttribute(k_msg<1>, cudaFuncAttributeMaxDynamicSharedMemorySize, SMEM_MSG);
  cudaFuncSetAttribute(k_final,  cudaFuncAttributeMaxDynamicSharedMemorySize, SMEM_FIN);

  k_init_h<<<NATOMS, FN>>>(Z, emb);
  k_init_e<<<NEDGE,  FE>>>(dist);

  for (int l = 0; l < 3; l++){
    int hin  = l & 1;          // 0,1,0  (h buffer holding current h)
    int hnew = 1 - hin;        // written by node update
    const float* wnf = Wnf + l*ZIN*FN;  const float* bnf_l = bnf + l*FN;
    const float* wnc = Wnc + l*ZIN*FN;  const float* bnc_l = bnc + l*FN;
    const float* wef = Wef + l*ZIN*FE;  const float* bef_l = bef + l*FE;
    const float* wec = Wec + l*ZIN*FE;  const float* bec_l = bec + l*FE;

    k_pre   <<<NATOMS, 256>>>(hin,  wnf, wnc, bnf_l, bnc_l);
    k_msg<0><<<NATOMS, 256, SMEM_MSG>>>(hin,  wnf, wnc, nbr);
    k_pre   <<<NATOMS, 256>>>(hnew, wef, wec, bef_l, bec_l);
    k_msg<1><<<NATOMS, 256, SMEM_MSG>>>(hnew, wef, wec, nbr);
  }

  k_final<<<NATOMS, 256, SMEM_FIN>>>(Wo1, bo1, Wo2, bo2, unit, out);
}

// round 3
// speedup vs baseline: 1.5547x; 1.5547x over previous
#include <cuda_runtime.h>
#include <cuda_bf16.h>
#include <cstdint>

#define B_      4
#define AT      1024
#define NBR     32
#define FN      128
#define FE      128
#define NATOMS  (B_*AT)        // 4096
#define NEDGE   (NATOMS*NBR)   // 131072
#define NCHUNK  12             // K = 384 in chunks of 32

// -------- device scratch --------
__device__ float g_h[2][NATOMS*FN];
__device__ float g_e[(size_t)NEDGE*FE];
// pre-split, pre-swizzled weight images: [gemm 6][chunk 12][prec 2][256 n x 32 k bf16] (16KB each)
__device__ __align__(16) __nv_bfloat16 g_Wimg[6*NCHUNK*2*8192];

__device__ __forceinline__ float sigm_(float x){ return 1.0f/(1.0f+expf(-x)); }
__device__ __forceinline__ float sp_(float x){ return fmaxf(x,0.f)+log1pf(expf(-fabsf(x))); }

__device__ __forceinline__ uint32_t smem_u32(const void* p){
  uint32_t a;
  asm("{ .reg .u64 t; cvta.to.shared.u64 t, %1; cvt.u32.u64 %0, t; }":"=r"(a):"l"(p));
  return a;
}

#define LDM4(r0,r1,r2,r3, addr) \
  asm volatile("ldmatrix.sync.aligned.m8n8.x4.shared.b16 {%0,%1,%2,%3}, [%4];" \
    : "=r"(r0),"=r"(r1),"=r"(r2),"=r"(r3) : "r"(addr))

#define MMA16816(d, a0,a1,a2,a3, b0,b1) \
  asm volatile("mma.sync.aligned.m16n8k16.row.col.f32.bf16.bf16.f32 " \
    "{%0,%1,%2,%3},{%4,%5,%6,%7},{%8,%9},{%0,%1,%2,%3};" \
    : "+f"(d[0]),"+f"(d[1]),"+f"(d[2]),"+f"(d[3]) \
    : "r"(a0),"r"(a1),"r"(a2),"r"(a3),"r"(b0),"r"(b1))

#define CP_ASYNC16(saddr, gptr) \
  asm volatile("cp.async.cg.shared.global [%0], [%1], 16;" :: "r"(saddr),"l"(gptr))
#define CP_COMMIT()  asm volatile("cp.async.commit_group;")
#define CP_WAIT0()   asm volatile("cp.async.wait_group 0;")

// pack 8 floats -> hi uint4 + lo uint4 (bf16 split)
__device__ __forceinline__ void pack8(const float* f, uint4& hi, uint4& lo){
  uint32_t h[4], l[4];
  #pragma unroll
  for (int i = 0; i < 4; i++){
    float a = f[2*i], b = f[2*i+1];
    __nv_bfloat162 hb = __floats2bfloat162_rn(a, b);
    float ra = a - __bfloat162float(hb.x);
    float rb = b - __bfloat162float(hb.y);
    __nv_bfloat162 lb = __floats2bfloat162_rn(ra, rb);
    h[i] = *(uint32_t*)&hb;  l[i] = *(uint32_t*)&lb;
  }
  hi = make_uint4(h[0],h[1],h[2],h[3]);
  lo = make_uint4(l[0],l[1],l[2],l[3]);
}

// -------------------- small kernels --------------------
__global__ void k_init_h(const int* __restrict__ Z, const float* __restrict__ emb){
  int a = blockIdx.x; int t = threadIdx.x;
  g_h[0][a*FN + t] = emb[Z[a]*FN + t];
}
__global__ void k_init_e(const float* __restrict__ dist){
  int eix = blockIdx.x*2 + (threadIdx.x>>7); int c = threadIdx.x & 127;
  float d = dist[eix];
  const float step = 5.5f/127.0f;
  float mu = c*step;
  float coeff = -0.5f/(step*step);
  float dd = d - mu;
  g_e[(size_t)eix*FE + c] = expf(coeff*dd*dd);
}

// weight prep: B[n][k] = W[k][n], bf16 hi/lo split, 16B-unit swizzle j^((n>>1)&3)
// grid: 6*12 blocks, 256 threads; thread t handles row n=t (32 k values)
__global__ void k_wprep(const float* __restrict__ Wnf, const float* __restrict__ Wnc,
                        const float* __restrict__ Wef, const float* __restrict__ Wec){
  int bid = blockIdx.x; int g = bid/NCHUNK, i = bid%NCHUNK;
  int l = g>>1; bool edge = g&1;
  const float* Wf = (edge? Wef:Wnf) + l*384*FN;
  const float* Wc = (edge? Wec:Wnc) + l*384*FN;
  int n = threadIdx.x;
  const float* W = (n < 128) ? (Wf + n) : (Wc + (n-128));
  float w[32];
  #pragma unroll
  for (int q = 0; q < 32; q++) w[q] = W[(i*32 + q)*FN];
  char* imgHi = (char*)g_Wimg + (size_t)((g*NCHUNK + i)*2    )*16384;
  char* imgLo = (char*)g_Wimg + (size_t)((g*NCHUNK + i)*2 + 1)*16384;
  #pragma unroll
  for (int j = 0; j < 4; j++){
    uint4 hi, lo; pack8(w + j*8, hi, lo);
    uint32_t off = (uint32_t)(n*4 + (j ^ ((n>>1)&3)))*16;
    *(uint4*)(imgHi + off) = hi;
    *(uint4*)(imgLo + off) = lo;
  }
}

// -------------------- HMMA message kernel --------------------
// Block = 4 atoms: D[128 rows x 256 cols] = z[128 x 384] @ Wcat[384 x 256] (+bias)
// smem: hj[128] ints @0, bias[256] @512B, stages @2048 (2 x 48KB)
//   stage: A_hi 8K | A_lo 8K | B_hi 16K | B_lo 16K
// epilogue reuse: Csh @2048 (128x132 f32), Msh @69632
#define SM_HJ    0
#define SM_BIAS  512
#define SM_STG   2048
#define STG_SZ   49152
#define SMEM_TC  137216

template<int MODE>
__global__ __launch_bounds__(256,1) void k_msg(int hsel, int g,
    const int* __restrict__ nbr_idx,
    const float* __restrict__ bf, const float* __restrict__ bc){
  extern __shared__ char smem[];
  const uint32_t sbase = smem_u32(smem);
  const int tid = threadIdx.x, lane = tid & 31, warp = tid >> 5;
  const int atom0 = blockIdx.x*4;
  const float* __restrict__ h_in = g_h[hsel];

  int*   hj   = (int*)(smem + SM_HJ);
  float* bias = (float*)(smem + SM_BIAS);
  if (tid < 128) hj[tid] = (atom0 >> 10)*AT + nbr_idx[atom0*NBR + tid];
  bias[tid] = (tid < 128) ? bf[tid] : bc[tid-128];

  // ---- A-build addressing (per thread: row m, 16 floats) ----
  const int m  = tid >> 1;
  const int hf = tid & 1;
  const uint32_t aoff0 = (uint32_t)m*64 + (uint32_t)(((hf*2 + 0) ^ ((m>>1)&3)))*16;
  const uint32_t aoff1 = (uint32_t)m*64 + (uint32_t)(((hf*2 + 1) ^ ((m>>1)&3)))*16;
  const char* wsrc = (const char*)g_Wimg + (size_t)(g*NCHUNK)*32768;

  auto srcA = [&](int i)->const float*{
    if (i < 4)      return h_in + (size_t)(atom0 + (m>>5))*FN + i*32 + hf*16;
    else if (i < 8) return h_in + (size_t)hj[m]*FN + (i-4)*32 + hf*16;
    else            return g_e + ((size_t)(atom0*NBR + m))*FE + (i-8)*32 + hf*16;
  };

  // ---- warp tile / fragment addressing ----
  const int wm = warp >> 2;            // 0..1  (m block of 64)
  const int wn = warp & 3;             // 0..3  (n block of 64)
  // A ldmatrix lane addr pieces
  const int ar  = (lane & 15);                         // row within 16
  const int aju = (lane >> 4);                         // unit add 0/1
  const int asw = ((ar >> 1) & 3);
  // B ldmatrix lane addr pieces
  const int br  = (lane & 7) + ((lane >> 4) << 3);     // row within 16
  const int bju = ((lane >> 3) & 1);
  const int bsw = ((br >> 1) & 3);

  float acc[4][8][4];
  #pragma unroll
  for (int i = 0; i < 4; i++)
    #pragma unroll
    for (int j = 0; j < 8; j++)
      #pragma unroll
      for (int q = 0; q < 4; q++) acc[i][j][q] = 0.f;

  __syncthreads();   // hj visible for srcA

  // ---- prologue: chunk 0 ----
  {
    const float* s = srcA(0);
    float4 p0 = *(const float4*)(s+0), p1 = *(const float4*)(s+4);
    float4 p2 = *(const float4*)(s+8), p3 = *(const float4*)(s+12);
    float fbuf[16];
    *(float4*)(fbuf+0)=p0; *(float4*)(fbuf+4)=p1; *(float4*)(fbuf+8)=p2; *(float4*)(fbuf+12)=p3;
    uint4 hi,lo;
    pack8(fbuf+0, hi, lo);
    *(uint4*)(smem + SM_STG + aoff0) = hi; *(uint4*)(smem + SM_STG + 8192 + aoff0) = lo;
    pack8(fbuf+8, hi, lo);
    *(uint4*)(smem + SM_STG + aoff1) = hi; *(uint4*)(smem + SM_STG + 8192 + aoff1) = lo;
    #pragma unroll
    for (int it = 0; it < 8; it++){
      uint32_t u = (uint32_t)(it*256 + tid)*16;
      CP_ASYNC16(sbase + SM_STG + 16384 + u, wsrc + u);
    }
    CP_COMMIT();
  }

  float pf[16]; bool havePf;
  for (int i = 0; i < NCHUNK; i++){
    const int s = i & 1;
    const uint32_t stg  = SM_STG + s*STG_SZ;
    const uint32_t nstg = SM_STG + (1-s)*STG_SZ;
    CP_WAIT0();
    __syncthreads();

    havePf = (i+1 < NCHUNK);
    if (havePf){
      const float* sp = srcA(i+1);
      *(float4*)(pf+0)  = *(const float4*)(sp+0);
      *(float4*)(pf+4)  = *(const float4*)(sp+4);
      *(float4*)(pf+8)  = *(const float4*)(sp+8);
      *(float4*)(pf+12) = *(const float4*)(sp+12);
      #pragma unroll
      for (int it = 0; it < 8; it++){
        uint32_t u = (uint32_t)(it*256 + tid)*16;
        CP_ASYNC16(sbase + nstg + 16384 + u, wsrc + (size_t)(i+1)*32768 + u);
      }
      CP_COMMIT();
    }

    // ---- MMA over chunk i: 2 ksteps of 16 ----
    const uint32_t Ahi = sbase + stg, Alo = Ahi + 8192;
    const uint32_t Bhi = sbase + stg + 16384, Blo = Bhi + 16384;
    #pragma unroll
    for (int kk = 0; kk < 2; kk++){
      uint32_t ah[4][4], al[4][4], bb[4][4];
      const uint32_t au = (uint32_t)((2*kk + aju) ^ asw)*16 + (uint32_t)ar*64;
      #pragma unroll
      for (int fm = 0; fm < 4; fm++){
        uint32_t ad = Ahi + (uint32_t)(wm*64 + fm*16)*64 + au;
        LDM4(ah[fm][0],ah[fm][1],ah[fm][2],ah[fm][3], ad);
      }
      #pragma unroll
      for (int fm = 0; fm < 4; fm++){
        uint32_t ad = Alo + (uint32_t)(wm*64 + fm*16)*64 + au;
        LDM4(al[fm][0],al[fm][1],al[fm][2],al[fm][3], ad);
      }
      const uint32_t bu = (uint32_t)((2*kk + bju) ^ bsw)*16 + (uint32_t)br*64;
      #pragma unroll
      for (int fn2 = 0; fn2 < 4; fn2++){
        uint32_t bd = Bhi + (uint32_t)(wn*64 + fn2*16)*64 + bu;
        LDM4(bb[fn2][0],bb[fn2][1],bb[fn2][2],bb[fn2][3], bd);
      }
      #pragma unroll
      for (int fm = 0; fm < 4; fm++)
        #pragma unroll
        for (int fn2 = 0; fn2 < 4; fn2++){
          MMA16816(acc[fm][fn2*2],   ah[fm][0],ah[fm][1],ah[fm][2],ah[fm][3], bb[fn2][0],bb[fn2][1]);
          MMA16816(acc[fm][fn2*2+1], ah[fm][0],ah[fm][1],ah[fm][2],ah[fm][3], bb[fn2][2],bb[fn2][3]);
        }
      #pragma unroll
      for (int fm = 0; fm < 4; fm++)
        #pragma unroll
        for (int fn2 = 0; fn2 < 4; fn2++){
          MMA16816(acc[fm][fn2*2],   al[fm][0],al[fm][1],al[fm][2],al[fm][3], bb[fn2][0],bb[fn2][1]);
          MMA16816(acc[fm][fn2*2+1], al[fm][0],al[fm][1],al[fm][2],al[fm][3], bb[fn2][2],bb[fn2][3]);
        }
      // reload B as lo, third product
      #pragma unroll
      for (int fn2 = 0; fn2 < 4; fn2++){
        uint32_t bd = Blo + (uint32_t)(wn*64 + fn2*16)*64 + bu;
        LDM4(bb[fn2][0],bb[fn2][1],bb[fn2][2],bb[fn2][3], bd);
      }
      #pragma unroll
      for (int fm = 0; fm < 4; fm++)
        #pragma unroll
        for (int fn2 = 0; fn2 < 4; fn2++){
          MMA16816(acc[fm][fn2*2],   ah[fm][0],ah[fm][1],ah[fm][2],ah[fm][3], bb[fn2][0],bb[fn2][1]);
          MMA16816(acc[fm][fn2*2+1], ah[fm][0],ah[fm][1],ah[fm][2],ah[fm][3], bb[fn2][2],bb[fn2][3]);
        }
    }

    if (havePf){
      uint4 hi,lo;
      pack8(pf+0, hi, lo);
      *(uint4*)(smem + nstg + aoff0) = hi; *(uint4*)(smem + nstg + 8192 + aoff0) = lo;
      pack8(pf+8, hi, lo);
      *(uint4*)(smem + nstg + aoff1) = hi; *(uint4*)(smem + nstg + 8192 + aoff1) = lo;
    }
  }
  __syncthreads();

  // ---- epilogue ----
  float* Csh = (float*)(smem + 2048);       // [128][132]
  float* Msh = (float*)(smem + 69632);      // [128][132]
  const bool isF = (wn < 2);
  const int  colb = wn*64 + (lane&3)*2;     // + fn*8
  const int  rowb = wm*64 + (lane>>2);      // + fm*16 (+8)

  if (!isF){
    #pragma unroll
    for (int fm = 0; fm < 4; fm++)
      #pragma unroll
      for (int fn = 0; fn < 8; fn++){
        int c = colb + fn*8 - 128;
        int r = rowb + fm*16;
        float bF0 = bias[128 + c], bF1 = bias[128 + c + 1];
        *(float2*)&Csh[r*132 + c]     = make_float2(sp_(acc[fm][fn][0]+bF0), sp_(acc[fm][fn][1]+bF1));
        *(float2*)&Csh[(r+8)*132 + c] = make_float2(sp_(acc[fm][fn][2]+bF0), sp_(acc[fm][fn][3]+bF1));
      }
  }
  __syncthreads();
  if (isF){
    #pragma unroll
    for (int fm = 0; fm < 4; fm++)
      #pragma unroll
      for (int fn = 0; fn < 8; fn++){
        int c = colb + fn*8;
        int r = rowb + fm*16;
        float bF0 = bias[c], bF1 = bias[c+1];
        float m0 = sigm_(acc[fm][fn][0]+bF0) * Csh[r*132 + c];
        float m1 = sigm_(acc[fm][fn][1]+bF1) * Csh[r*132 + c + 1];
        float m2 = sigm_(acc[fm][fn][2]+bF0) * Csh[(r+8)*132 + c];
        float m3 = sigm_(acc[fm][fn][3]+bF1) * Csh[(r+8)*132 + c + 1];
        *(float2*)&Msh[r*132 + c]     = make_float2(m0, m1);
        *(float2*)&Msh[(r+8)*132 + c] = make_float2(m2, m3);
      }
  }
  __syncthreads();

  if (MODE == 0){
    #pragma unroll
    for (int p = 0; p < 2; p++){
      int a = (tid >> 7) + p*2;
      int c = tid & 127;
      float s = 0.f;
      #pragma unroll 8
      for (int r = 0; r < 32; r++) s += Msh[(a*32 + r)*132 + c];
      int gi = (atom0 + a)*FN + c;
      g_h[1-hsel][gi] = h_in[gi] + s;
    }
  } else {
    int r = tid >> 1;
    int c0 = (tid & 1)*64;
    float* dst = g_e + ((size_t)(atom0*NBR + r))*FE + c0;
    #pragma unroll
    for (int q = 0; q < 16; q++){
      float4 o = *(float4*)(dst + q*4);
      const float* ms = &Msh[r*132 + c0 + q*4];
      *(float4*)(dst + q*4) = make_float4(o.x+ms[0], o.y+ms[1], o.z+ms[2], o.w+ms[3]);
    }
  }
}

// ---------- force-magnitude mapping + force reduction ----------
#define SMEM_FIN ((32*128 + 128*64 + 32)*4)
__global__ __launch_bounds__(256) void k_final(
    const float* __restrict__ Wo1, const float* __restrict__ bo1,
    const float* __restrict__ Wo2, const float* __restrict__ bo2,
    const float* __restrict__ unit, float* __restrict__ out){
  extern __shared__ float smemf[];
  float* es = smemf;
  float* w1 = smemf + 32*128;
  float* fm = w1 + 128*64;
  int a = blockIdx.x; int tid = threadIdx.x;
  #pragma unroll
  for (int i = 0; i < 16; i++) es[i*256 + tid] = g_e[(size_t)a*NBR*FE + i*256 + tid];
  #pragma unroll
  for (int i = 0; i < 32; i++) w1[i*256 + tid] = Wo1[i*256 + tid];
  __syncthreads();

  int n  = tid >> 3;
  int m0 = (tid & 7) * 8;
  float acc[8];
  #pragma unroll
  for (int m = 0; m < 8; m++) acc[m] = bo1[m0+m];
  for (int k = 0; k < 128; k++){
    float ek = es[n*128 + k];
    float4 wa = *(float4*)&w1[k*64 + m0];
    float4 wb = *(float4*)&w1[k*64 + m0 + 4];
    acc[0] = fmaf(ek, wa.x, acc[0]); acc[1] = fmaf(ek, wa.y, acc[1]);
    acc[2] = fmaf(ek, wa.z, acc[2]); acc[3] = fmaf(ek, wa.w, acc[3]);
    acc[4] = fmaf(ek, wb.x, acc[4]); acc[5] = fmaf(ek, wb.y, acc[5]);
    acc[6] = fmaf(ek, wb.z, acc[6]); acc[7] = fmaf(ek, wb.w, acc[7]);
  }
  float part = 0.f;
  #pragma unroll
  for (int m = 0; m < 8; m++) part += sp_(acc[m]) * Wo2[m0+m];
  part += __shfl_xor_sync(0xffffffffu, part, 4);
  part += __shfl_xor_sync(0xffffffffu, part, 2);
  part += __shfl_xor_sync(0xffffffffu, part, 1);
  if ((tid & 7) == 0) fm[n] = part + bo2[0];
  __syncthreads();
  if (tid < 3){
    float s = 0.f;
    #pragma unroll 8
    for (int n2 = 0; n2 < NBR; n2++)
      s += fm[n2] * unit[((size_t)a*NBR + n2)*3 + tid];
    out[a*3 + tid] = s;
  }
}

extern "C" void kernel_launch(void* const* d_in, const int* in_sizes, int n_in,
                              void* d_out, int out_size){
  const int*   Z    = (const int*)  d_in[0];
  const int*   nbr  = (const int*)  d_in[1];
  const float* dist = (const float*)d_in[2];
  const float* unit = (const float*)d_in[3];
  const float* emb  = (const float*)d_in[4];
  const float* Wnf  = (const float*)d_in[5];
  const float* bnf  = (const float*)d_in[6];
  const float* Wnc  = (const float*)d_in[7];
  const float* bnc  = (const float*)d_in[8];
  const float* Wef  = (const float*)d_in[9];
  const float* bef  = (const float*)d_in[10];
  const float* Wec  = (const float*)d_in[11];
  const float* bec  = (const float*)d_in[12];
  const float* Wo1  = (const float*)d_in[13];
  const float* bo1  = (const float*)d_in[14];
  const float* Wo2  = (const float*)d_in[15];
  const float* bo2  = (const float*)d_in[16];
  float* out = (float*)d_out;

  cudaFuncSetAttribute(k_msg<0>, cudaFuncAttributeMaxDynamicSharedMemorySize, SMEM_TC);
  cudaFuncSetAttribute(k_msg<1>, cudaFuncAttributeMaxDynamicSharedMemorySize, SMEM_TC);
  cudaFuncSetAttribute(k_final,  cudaFuncAttributeMaxDynamicSharedMemorySize, SMEM_FIN);

  k_wprep <<<6*NCHUNK, 256>>>(Wnf, Wnc, Wef, Wec);
  k_init_h<<<NATOMS, FN>>>(Z, emb);
  k_init_e<<<NEDGE/2, 256>>>(dist);

  for (int l = 0; l < 3; l++){
    int hin  = l & 1;
    int hnew = 1 - hin;
    k_msg<0><<<NATOMS/4, 256, SMEM_TC>>>(hin,  l*2,   nbr, bnf + l*FN, bnc + l*FN);
    k_msg<1><<<NATOMS/4, 256, SMEM_TC>>>(hnew, l*2+1, nbr, bef + l*FE, bec + l*FE);
  }

  k_final<<<NATOMS, 256, SMEM_FIN>>>(Wo1, bo1, Wo2, bo2, unit, out);
}

// round 4
// speedup vs baseline: 2.0727x; 1.3332x over previous
#include <cuda_runtime.h>
#include <cuda_bf16.h>
#include <cstdint>

#define B_      4
#define AT      1024
#define NBR     32
#define FN      128
#define FE      128
#define NATOMS  (B_*AT)        // 4096
#define NEDGE   (NATOMS*NBR)   // 131072
#define NCHUNK  12             // K = 384 in chunks of 32

// -------- device scratch --------
__device__ float g_h[2][NATOMS*FN];
__device__ float g_e[(size_t)NEDGE*FE];
__device__ __nv_bfloat16 g_hS[2][2][NATOMS*FN];          // [pingpong][hi/lo]
__device__ __nv_bfloat16 g_eS[2][(size_t)NEDGE*FE];      // [hi/lo]
// pre-split, pre-swizzled weights: [gemm 6][chunk 12][hi/lo][256 n x 32 k bf16]
__device__ __align__(16) __nv_bfloat16 g_Wimg[6*NCHUNK*2*8192];

__device__ __forceinline__ float sigm_(float x){ return 1.0f/(1.0f+expf(-x)); }
__device__ __forceinline__ float sp_(float x){ return fmaxf(x,0.f)+log1pf(expf(-fabsf(x))); }

__device__ __forceinline__ uint32_t smem_u32(const void* p){
  uint32_t a;
  asm("{ .reg .u64 t; cvta.to.shared.u64 t, %1; cvt.u32.u64 %0, t; }":"=r"(a):"l"(p));
  return a;
}

#define LDM4(r0,r1,r2,r3, addr) \
  asm volatile("ldmatrix.sync.aligned.m8n8.x4.shared.b16 {%0,%1,%2,%3}, [%4];" \
    : "=r"(r0),"=r"(r1),"=r"(r2),"=r"(r3) : "r"(addr))

#define MMA16816(d, a0,a1,a2,a3, b0,b1) \
  asm volatile("mma.sync.aligned.m16n8k16.row.col.f32.bf16.bf16.f32 " \
    "{%0,%1,%2,%3},{%4,%5,%6,%7},{%8,%9},{%0,%1,%2,%3};" \
    : "+f"(d[0]),"+f"(d[1]),"+f"(d[2]),"+f"(d[3]) \
    : "r"(a0),"r"(a1),"r"(a2),"r"(a3),"r"(b0),"r"(b1))

#define CP_ASYNC16(saddr, gptr) \
  asm volatile("cp.async.cg.shared.global [%0], [%1], 16;" :: "r"(saddr),"l"(gptr))
#define CP_COMMIT()  asm volatile("cp.async.commit_group;")
#define CP_WAIT0()   asm volatile("cp.async.wait_group 0;")

__device__ __forceinline__ void pack8(const float* f, uint4& hi, uint4& lo){
  uint32_t h[4], l[4];
  #pragma unroll
  for (int i = 0; i < 4; i++){
    float a = f[2*i], b = f[2*i+1];
    __nv_bfloat162 hb = __floats2bfloat162_rn(a, b);
    float ra = a - __bfloat162float(hb.x);
    float rb = b - __bfloat162float(hb.y);
    __nv_bfloat162 lb = __floats2bfloat162_rn(ra, rb);
    h[i] = *(uint32_t*)&hb;  l[i] = *(uint32_t*)&lb;
  }
  hi = make_uint4(h[0],h[1],h[2],h[3]);
  lo = make_uint4(l[0],l[1],l[2],l[3]);
}

// -------------------- init kernels --------------------
__global__ void k_init_h(const int* __restrict__ Z, const float* __restrict__ emb){
  int a = blockIdx.x; int t = threadIdx.x;
  float v = emb[Z[a]*FN + t];
  int gi = a*FN + t;
  g_h[0][gi] = v;
  __nv_bfloat16 hi = __float2bfloat16(v);
  g_hS[0][0][gi] = hi;
  g_hS[0][1][gi] = __float2bfloat16(v - __bfloat162float(hi));
}
__global__ void k_init_e(const float* __restrict__ dist){
  int eix = blockIdx.x*2 + (threadIdx.x>>7); int c = threadIdx.x & 127;
  float d = dist[eix];
  const float step = 5.5f/127.0f;
  float mu = c*step;
  float coeff = -0.5f/(step*step);
  float dd = d - mu;
  float v = expf(coeff*dd*dd);
  size_t gi = (size_t)eix*FE + c;
  g_e[gi] = v;
  __nv_bfloat16 hi = __float2bfloat16(v);
  g_eS[0][gi] = hi;
  g_eS[1][gi] = __float2bfloat16(v - __bfloat162float(hi));
}

// weight prep: B[n][k]=W[k][n], hi/lo split, 16B-unit swizzle j^((n>>1)&3), row stride 64B
__global__ void k_wprep(const float* __restrict__ Wnf, const float* __restrict__ Wnc,
                        const float* __restrict__ Wef, const float* __restrict__ Wec){
  int bid = blockIdx.x; int g = bid/NCHUNK, i = bid%NCHUNK;
  int l = g>>1; bool edge = g&1;
  const float* Wf = (edge? Wef:Wnf) + l*384*FN;
  const float* Wc = (edge? Wec:Wnc) + l*384*FN;
  int n = threadIdx.x;
  const float* W = (n < 128) ? (Wf + n) : (Wc + (n-128));
  float w[32];
  #pragma unroll
  for (int q = 0; q < 32; q++) w[q] = W[(i*32 + q)*FN];
  char* imgHi = (char*)g_Wimg + (size_t)((g*NCHUNK + i)*2    )*16384;
  char* imgLo = (char*)g_Wimg + (size_t)((g*NCHUNK + i)*2 + 1)*16384;
  #pragma unroll
  for (int j = 0; j < 4; j++){
    uint4 hi, lo; pack8(w + j*8, hi, lo);
    uint32_t off = (uint32_t)(n*4 + (j ^ ((n>>1)&3)))*16;
    *(uint4*)(imgHi + off) = hi;
    *(uint4*)(imgLo + off) = lo;
  }
}

// -------------------- HMMA message kernel --------------------
// 512 threads, 16 warps; block = 4 atoms; D[128 x 256] = z[128 x 384] @ W[384 x 256]
// warp tile 64x32: wm = warp>>3 (2), wn = warp&7 (8)
// smem: hj[128] @0, bias[256] @512, stages @2048 (2 x 48K: Ahi 8K|Alo 8K|Bhi 16K|Blo 16K)
// epilogue: Csh @2048 [128][132], Msh @69632 [128][132]
#define SM_STG   2048
#define STG_SZ   49152
#define SMEM_TC  137216

template<int MODE>
__global__ __launch_bounds__(512,1) void k_msg(int hsel, int g,
    const int* __restrict__ nbr_idx,
    const float* __restrict__ bfp, const float* __restrict__ bcp){
  extern __shared__ char smem[];
  const uint32_t sbase = smem_u32(smem);
  const int tid = threadIdx.x, lane = tid & 31, warp = tid >> 5;
  const int atom0 = blockIdx.x*4;

  int*   hj   = (int*)smem;
  float* bias = (float*)(smem + 512);
  if (tid < 128) hj[tid] = (atom0 >> 10)*AT + nbr_idx[atom0*NBR + tid];
  if (tid >= 128 && tid < 384) bias[tid-128] = (tid < 256) ? bfp[tid-128] : bcp[tid-256];

  // ---- A cp.async addressing: thread -> (prec, row, 2 units of 16B) ----
  const int aprec = tid >> 8;
  const int arow  = (tid & 255) >> 1;
  const int ajj   = (tid & 1) * 2;
  const int asw4  = (arow >> 1) & 3;
  const uint32_t aoff0 = (uint32_t)(aprec*8192 + arow*64 + ((ajj     ^ asw4)<<4));
  const uint32_t aoff1 = (uint32_t)(aprec*8192 + arow*64 + (((ajj+1) ^ asw4)<<4));
  const __nv_bfloat16* himg = g_hS[hsel][aprec];
  const __nv_bfloat16* eimg = g_eS[aprec];
  const char* wbase = (const char*)g_Wimg + (size_t)g*NCHUNK*32768;

  auto loadA = [&](int i, uint32_t ss){
    const __nv_bfloat16* src;
    if (i < 4)      src = himg + (size_t)(atom0 + (arow>>5))*FN + i*32 + ajj*8;
    else if (i < 8) src = himg + (size_t)hj[arow]*FN + (i-4)*32 + ajj*8;
    else            src = eimg + ((size_t)(atom0*NBR + arow))*FE + (i-8)*32 + ajj*8;
    CP_ASYNC16(sbase + ss + aoff0, src);
    CP_ASYNC16(sbase + ss + aoff1, src + 8);
  };
  auto loadB = [&](int i, uint32_t ss){
    const char* src = wbase + (size_t)i*32768;
    #pragma unroll
    for (int it = 0; it < 4; it++){
      uint32_t u = (uint32_t)(it*512 + tid)*16;
      CP_ASYNC16(sbase + ss + 16384 + u, src + u);
    }
  };

  // ---- fragment addressing ----
  const int wm = warp >> 3;            // 0..1
  const int wn = warp & 7;             // 0..7
  const int ar  = lane & 15;
  const int aju = lane >> 4;
  const int asw = (ar >> 1) & 3;
  const int br  = (lane & 7) + ((lane >> 4) << 3);
  const int bju = (lane >> 3) & 1;
  const int bsw = (br >> 1) & 3;

  float acc[4][4][4];
  #pragma unroll
  for (int i=0;i<4;i++)
    #pragma unroll
    for (int j=0;j<4;j++)
      #pragma unroll
      for (int q=0;q<4;q++) acc[i][j][q]=0.f;

  __syncthreads();
  loadA(0, SM_STG); loadB(0, SM_STG); CP_COMMIT();

  for (int i = 0; i < NCHUNK; i++){
    const uint32_t ss = SM_STG + (uint32_t)(i&1)*STG_SZ;
    const uint32_t ns = SM_STG + (uint32_t)((i+1)&1)*STG_SZ;
    CP_WAIT0();
    __syncthreads();
    if (i+1 < NCHUNK){ loadA(i+1, ns); loadB(i+1, ns); CP_COMMIT(); }

    const uint32_t Ahi = sbase + ss, Alo = Ahi + 8192;
    const uint32_t Bhi = sbase + ss + 16384, Blo = Bhi + 16384;
    #pragma unroll
    for (int kk = 0; kk < 2; kk++){
      const uint32_t au = (uint32_t)((2*kk + aju) ^ asw)*16 + (uint32_t)ar*64;
      const uint32_t bu = (uint32_t)((2*kk + bju) ^ bsw)*16 + (uint32_t)br*64;
      uint32_t ah[4][4], bb[2][4];
      #pragma unroll
      for (int fm = 0; fm < 4; fm++)
        LDM4(ah[fm][0],ah[fm][1],ah[fm][2],ah[fm][3],
             Ahi + (uint32_t)(wm*64 + fm*16)*64 + au);
      #pragma unroll
      for (int fb = 0; fb < 2; fb++)
        LDM4(bb[fb][0],bb[fb][1],bb[fb][2],bb[fb][3],
             Bhi + (uint32_t)(wn*32 + fb*16)*64 + bu);
      #pragma unroll
      for (int fm = 0; fm < 4; fm++)
        #pragma unroll
        for (int fb = 0; fb < 2; fb++){
          MMA16816(acc[fm][fb*2],   ah[fm][0],ah[fm][1],ah[fm][2],ah[fm][3], bb[fb][0],bb[fb][1]);
          MMA16816(acc[fm][fb*2+1], ah[fm][0],ah[fm][1],ah[fm][2],ah[fm][3], bb[fb][2],bb[fb][3]);
        }
      uint32_t al[4][4];
      #pragma unroll
      for (int fm = 0; fm < 4; fm++)
        LDM4(al[fm][0],al[fm][1],al[fm][2],al[fm][3],
             Alo + (uint32_t)(wm*64 + fm*16)*64 + au);
      #pragma unroll
      for (int fm = 0; fm < 4; fm++)
        #pragma unroll
        for (int fb = 0; fb < 2; fb++){
          MMA16816(acc[fm][fb*2],   al[fm][0],al[fm][1],al[fm][2],al[fm][3], bb[fb][0],bb[fb][1]);
          MMA16816(acc[fm][fb*2+1], al[fm][0],al[fm][1],al[fm][2],al[fm][3], bb[fb][2],bb[fb][3]);
        }
      #pragma unroll
      for (int fb = 0; fb < 2; fb++)
        LDM4(bb[fb][0],bb[fb][1],bb[fb][2],bb[fb][3],
             Blo + (uint32_t)(wn*32 + fb*16)*64 + bu);
      #pragma unroll
      for (int fm = 0; fm < 4; fm++)
        #pragma unroll
        for (int fb = 0; fb < 2; fb++){
          MMA16816(acc[fm][fb*2],   ah[fm][0],ah[fm][1],ah[fm][2],ah[fm][3], bb[fb][0],bb[fb][1]);
          MMA16816(acc[fm][fb*2+1], ah[fm][0],ah[fm][1],ah[fm][2],ah[fm][3], bb[fb][2],bb[fb][3]);
        }
    }
  }
  __syncthreads();

  // ---- epilogue ----
  float* Csh = (float*)(smem + 2048);        // [128][132] sp(C)
  float* Msh = (float*)(smem + 69632);       // [128][132] (MODE 1)

  if (wn >= 4){
    #pragma unroll
    for (int fm = 0; fm < 4; fm++)
      #pragma unroll
      for (int fn = 0; fn < 4; fn++){
        int c = (wn-4)*32 + fn*8 + (lane&3)*2;
        int r = wm*64 + fm*16 + (lane>>2);
        float b0 = bias[128 + c], b1 = bias[128 + c + 1];
        Csh[r*132 + c]       = sp_(acc[fm][fn][0] + b0);
        Csh[r*132 + c + 1]   = sp_(acc[fm][fn][1] + b1);
        Csh[(r+8)*132 + c]   = sp_(acc[fm][fn][2] + b0);
        Csh[(r+8)*132 + c+1] = sp_(acc[fm][fn][3] + b1);
      }
  }
  __syncthreads();

  if (MODE == 0){
    if (wn < 4){
      float sA[2][4][2];
      #pragma unroll
      for (int a2=0;a2<2;a2++)
        #pragma unroll
        for (int fn=0;fn<4;fn++){ sA[a2][fn][0]=0.f; sA[a2][fn][1]=0.f; }
      #pragma unroll
      for (int fm = 0; fm < 4; fm++){
        int a2 = fm >> 1;
        #pragma unroll
        for (int fn = 0; fn < 4; fn++){
          int c = wn*32 + fn*8 + (lane&3)*2;
          int r = wm*64 + fm*16 + (lane>>2);
          float b0 = bias[c], b1 = bias[c+1];
          float m0 = sigm_(acc[fm][fn][0] + b0) * Csh[r*132 + c];
          float m1 = sigm_(acc[fm][fn][1] + b1) * Csh[r*132 + c + 1];
          float m2 = sigm_(acc[fm][fn][2] + b0) * Csh[(r+8)*132 + c];
          float m3 = sigm_(acc[fm][fn][3] + b1) * Csh[(r+8)*132 + c + 1];
          sA[a2][fn][0] += m0 + m2;
          sA[a2][fn][1] += m1 + m3;
        }
      }
      #pragma unroll
      for (int a2=0;a2<2;a2++)
        #pragma unroll
        for (int fn=0;fn<4;fn++)
          #pragma unroll
          for (int p=0;p<2;p++){
            float v = sA[a2][fn][p];
            v += __shfl_xor_sync(0xffffffffu, v, 4);
            v += __shfl_xor_sync(0xffffffffu, v, 8);
            v += __shfl_xor_sync(0xffffffffu, v, 16);
            sA[a2][fn][p] = v;
          }
      if (lane < 4){
        #pragma unroll
        for (int a2=0;a2<2;a2++){
          int ag = atom0 + wm*2 + a2;
          #pragma unroll
          for (int fn=0;fn<4;fn++){
            int c = wn*32 + fn*8 + lane*2;
            #pragma unroll
            for (int p=0;p<2;p++){
              int gi = ag*FN + c + p;
              float hn = g_h[hsel][gi] + sA[a2][fn][p];
              g_h[1-hsel][gi] = hn;
              __nv_bfloat16 hb = __float2bfloat16(hn);
              g_hS[1-hsel][0][gi] = hb;
              g_hS[1-hsel][1][gi] = __float2bfloat16(hn - __bfloat162float(hb));
            }
          }
        }
      }
    }
  } else {
    if (wn < 4){
      #pragma unroll
      for (int fm = 0; fm < 4; fm++)
        #pragma unroll
        for (int fn = 0; fn < 4; fn++){
          int c = wn*32 + fn*8 + (lane&3)*2;
          int r = wm*64 + fm*16 + (lane>>2);
          float b0 = bias[c], b1 = bias[c+1];
          Msh[r*132 + c]       = sigm_(acc[fm][fn][0] + b0) * Csh[r*132 + c];
          Msh[r*132 + c + 1]   = sigm_(acc[fm][fn][1] + b1) * Csh[r*132 + c + 1];
          Msh[(r+8)*132 + c]   = sigm_(acc[fm][fn][2] + b0) * Csh[(r+8)*132 + c];
          Msh[(r+8)*132 + c+1] = sigm_(acc[fm][fn][3] + b1) * Csh[(r+8)*132 + c + 1];
        }
    }
    __syncthreads();
    // coalesced writeback: thread -> row tid>>2, 8-col group (tid&3)*8 + q*32
    int row = tid >> 2;
    size_t erow = (size_t)(atom0*NBR + row)*FE;
    #pragma unroll
    for (int q = 0; q < 4; q++){
      int c = (tid&3)*8 + q*32;
      float en[8];
      #pragma unroll
      for (int u = 0; u < 8; u++)
        en[u] = g_e[erow + c + u] + Msh[row*132 + c + u];
      *(float4*)&g_e[erow + c]     = make_float4(en[0],en[1],en[2],en[3]);
      *(float4*)&g_e[erow + c + 4] = make_float4(en[4],en[5],en[6],en[7]);
      uint4 hi, lo; pack8(en, hi, lo);
      *(uint4*)&g_eS[0][erow + c] = hi;
      *(uint4*)&g_eS[1][erow + c] = lo;
    }
  }
}

// ---------- force-magnitude mapping + force reduction (4 atoms/block) ----------
#define SMEM_FIN (128*132*4 + 128*64*4 + 128*4)   // 100864
__global__ __launch_bounds__(512) void k_final(
    const float* __restrict__ Wo1, const float* __restrict__ bo1,
    const float* __restrict__ Wo2, const float* __restrict__ bo2,
    const float* __restrict__ unit, float* __restrict__ out){
  extern __shared__ float smemf[];
  float* es  = smemf;                 // [128][132]
  float* w1  = smemf + 128*132;       // [128][64]
  float* fmv = w1 + 128*64;           // [128]
  int a0 = blockIdx.x*4; int tid = threadIdx.x;

  #pragma unroll
  for (int it = 0; it < 8; it++){
    int v = it*512 + tid;
    int row = v >> 5, c4 = (v & 31);
    float4 x = ((const float4*)(g_e + (size_t)(a0*NBR + row)*FE))[c4];
    *(float4*)&es[row*132 + c4*4] = x;
  }
  #pragma unroll
  for (int it = 0; it < 4; it++){
    int v = it*512 + tid;
    ((float4*)w1)[v] = ((const float4*)Wo1)[v];
  }
  __syncthreads();

  int n  = tid >> 2;
  int m0 = (tid & 3) * 16;
  float acc[16];
  #pragma unroll
  for (int m = 0; m < 16; m++) acc[m] = bo1[m0+m];
  for (int k = 0; k < 128; k++){
    float ek = es[n*132 + k];
    #pragma unroll
    for (int u = 0; u < 4; u++){
      float4 w = *(float4*)&w1[k*64 + m0 + u*4];
      acc[u*4+0] = fmaf(ek, w.x, acc[u*4+0]);
      acc[u*4+1] = fmaf(ek, w.y, acc[u*4+1]);
      acc[u*4+2] = fmaf(ek, w.z, acc[u*4+2]);
      acc[u*4+3] = fmaf(ek, w.w, acc[u*4+3]);
    }
  }
  float part = 0.f;
  #pragma unroll
  for (int m = 0; m < 16; m++) part += sp_(acc[m]) * Wo2[m0+m];
  part += __shfl_xor_sync(0xffffffffu, part, 1);
  part += __shfl_xor_sync(0xffffffffu, part, 2);
  if ((tid & 3) == 0) fmv[n] = part + bo2[0];
  __syncthreads();
  if (tid < 12){
    int atom = tid/3, comp = tid%3;
    float s = 0.f;
    #pragma unroll 8
    for (int r = 0; r < 32; r++)
      s += fmv[atom*32 + r] * unit[((size_t)(a0+atom)*NBR + r)*3 + comp];
    out[(a0+atom)*3 + comp] = s;
  }
}

extern "C" void kernel_launch(void* const* d_in, const int* in_sizes, int n_in,
                              void* d_out, int out_size){
  const int*   Z    = (const int*)  d_in[0];
  const int*   nbr  = (const int*)  d_in[1];
  const float* dist = (const float*)d_in[2];
  const float* unit = (const float*)d_in[3];
  const float* emb  = (const float*)d_in[4];
  const float* Wnf  = (const float*)d_in[5];
  const float* bnf  = (const float*)d_in[6];
  const float* Wnc  = (const float*)d_in[7];
  const float* bnc  = (const float*)d_in[8];
  const float* Wef  = (const float*)d_in[9];
  const float* bef  = (const float*)d_in[10];
  const float* Wec  = (const float*)d_in[11];
  const float* bec  = (const float*)d_in[12];
  const float* Wo1  = (const float*)d_in[13];
  const float* bo1  = (const float*)d_in[14];
  const float* Wo2  = (const float*)d_in[15];
  const float* bo2  = (const float*)d_in[16];
  float* out = (float*)d_out;

  cudaFuncSetAttribute(k_msg<0>, cudaFuncAttributeMaxDynamicSharedMemorySize, SMEM_TC);
  cudaFuncSetAttribute(k_msg<1>, cudaFuncAttributeMaxDynamicSharedMemorySize, SMEM_TC);
  cudaFuncSetAttribute(k_final,  cudaFuncAttributeMaxDynamicSharedMemorySize, SMEM_FIN);

  k_wprep <<<6*NCHUNK, 256>>>(Wnf, Wnc, Wef, Wec);
  k_init_h<<<NATOMS, FN>>>(Z, emb);
  k_init_e<<<NEDGE/2, 256>>>(dist);

  for (int l = 0; l < 3; l++){
    int hin  = l & 1;
    int hnew = 1 - hin;
    k_msg<0><<<NATOMS/4, 512, SMEM_TC>>>(hin,  l*2,   nbr, bnf + l*FN, bnc + l*FN);
    k_msg<1><<<NATOMS/4, 512, SMEM_TC>>>(hnew, l*2+1, nbr, bef + l*FE, bec + l*FE);
  }

  k_final<<<NATOMS/4, 512, SMEM_FIN>>>(Wo1, bo1, Wo2, bo2, unit, out);
}